// round 1
// baseline (speedup 1.0000x reference)
#include <cuda_runtime.h>

// ---------------- problem constants ----------------
#define BB   2
#define CC   24
#define KQ   7
#define KK   49            // KQ*KQ
#define HH   256
#define WW   256
#define CO   1176          // CC*KK
#define PLANE 65536        // HH*WW
#define NPIX  131072       // BB*PLANE

// ---------------- device scratch (no allocs allowed) ----------------
__device__ float g_E[(size_t)CO * NPIX];   // unnormalized exp(logits), plane-major: [o][b*PLANE + y*W + x]
__device__ float g_Sinv[NPIX];             // 1/sum(exp) per pixel
__device__ float g_lat[BB * CC * PLANE];   // depth_latent
__device__ float g_dA[BB * CC * PLANE];    // diffusion ping
__device__ float g_dB[BB * CC * PLANE];    // diffusion pong

// ================= K1: depth_latent = conv3x3(depth; 1 -> 24) =================
__global__ void k_lat(const float* __restrict__ depth,
                      const float* __restrict__ w_dp,
                      const float* __restrict__ b_dp) {
    __shared__ float sD[3][WW + 2];
    __shared__ float sW[CC * 9];
    __shared__ float sB[CC];
    const int bid = blockIdx.x;          // b*HH + y
    const int b = bid >> 8, y = bid & 255;
    const int tid = threadIdx.x;

    for (int i = tid; i < CC * 9; i += blockDim.x) sW[i] = w_dp[i];
    if (tid < CC) sB[tid] = b_dp[tid];

    const float* dp = depth + (size_t)b * PLANE;
    for (int r = 0; r < 3; r++) {
        const int yy = y + r - 1;
        for (int xx = tid; xx < WW + 2; xx += blockDim.x) {
            const int gx = xx - 1;
            sD[r][xx] = (yy >= 0 && yy < HH && gx >= 0 && gx < WW) ? dp[yy * WW + gx] : 0.f;
        }
    }
    __syncthreads();

    float p[9];
#pragma unroll
    for (int r = 0; r < 3; r++)
#pragma unroll
        for (int cx = 0; cx < 3; cx++) p[r * 3 + cx] = sD[r][tid + cx];

    for (int co = 0; co < CC; co++) {
        float acc = sB[co];
#pragma unroll
        for (int j = 0; j < 9; j++) acc = fmaf(sW[co * 9 + j], p[j], acc);
        g_lat[((size_t)(b * CC + co) * HH + y) * WW + tid] = acc;
    }
}

// ================= K2: logits conv (3 -> 1176) + exp + per-pixel sum =================
// One block per image row (256 pixels), one thread per pixel.
// Weights staged through smem in 4 chunks of 294 outputs (fits 48KB static smem).
#define OCHUNK 294
__global__ void k_softmax(const float* __restrict__ tex,
                          const float* __restrict__ w_kp,
                          const float* __restrict__ b_kp) {
    __shared__ __align__(16) float sW[OCHUNK * 28];   // 27 weights + 1 pad per output
    __shared__ float sT[3][3][WW + 2];

    const int bid = blockIdx.x;          // b*HH + y
    const int b = bid >> 8, y = bid & 255;
    const int tid = threadIdx.x;

    // stage texture rows (3 channels, rows y-1..y+1, zero-padded)
    for (int ch = 0; ch < 3; ch++) {
        const float* tp = tex + (size_t)(b * 3 + ch) * PLANE;
        for (int r = 0; r < 3; r++) {
            const int yy = y + r - 1;
            for (int xx = tid; xx < WW + 2; xx += blockDim.x) {
                const int gx = xx - 1;
                sT[ch][r][xx] = (yy >= 0 && yy < HH && gx >= 0 && gx < WW) ? tp[yy * WW + gx] : 0.f;
            }
        }
    }

    float p[27];
    float S = 0.f;
    const size_t pix = (size_t)b * PLANE + (size_t)y * WW + tid;
    bool first = true;

    for (int ochunk = 0; ochunk < CO; ochunk += OCHUNK) {
        __syncthreads();   // previous chunk fully consumed; (first iter: sT writes done)
        for (int i = tid; i < OCHUNK * 27; i += blockDim.x) {
            const int o = i / 27, j = i - o * 27;
            sW[o * 28 + j] = w_kp[(size_t)(ochunk + o) * 27 + j];
        }
        __syncthreads();

        if (first) {
#pragma unroll
            for (int ch = 0; ch < 3; ch++)
#pragma unroll
                for (int r = 0; r < 3; r++)
#pragma unroll
                    for (int cx = 0; cx < 3; cx++)
                        p[(ch * 3 + r) * 3 + cx] = sT[ch][r][tid + cx];
            first = false;
        }

        for (int ol = 0; ol < OCHUNK; ol++) {
            float wr[28];
            float4* wr4 = reinterpret_cast<float4*>(wr);
            const float4* src4 = reinterpret_cast<const float4*>(&sW[ol * 28]);
#pragma unroll
            for (int q = 0; q < 7; q++) wr4[q] = src4[q];

            float a0 = b_kp[ochunk + ol], a1 = 0.f, a2 = 0.f, a3 = 0.f;
#pragma unroll
            for (int j = 0; j < 27; j += 4) {
                a0 = fmaf(wr[j], p[j], a0);
                if (j + 1 < 27) a1 = fmaf(wr[j + 1], p[j + 1], a1);
                if (j + 2 < 27) a2 = fmaf(wr[j + 2], p[j + 2], a2);
                if (j + 3 < 27) a3 = fmaf(wr[j + 3], p[j + 3], a3);
            }
            const float e = __expf((a0 + a1) + (a2 + a3));
            S += e;
            g_E[(size_t)(ochunk + ol) * NPIX + pix] = e;
        }
    }
    g_Sinv[pix] = 1.f / S;
}

// ================= K3..K6: one diffusion iteration =================
// diffused[c](p) = (sum_t E[c*49+t](p) * in[c](p + delta_t)) * Sinv(p)
// Block: 256 threads = one x-row span; handles RROWS rows of one (b, c) plane.
#define RROWS 8
__global__ void k_diff(int srcSel, int dstSel) {
    __shared__ float sIn[RROWS + 6][WW + 8];
    const int tid = threadIdx.x;
    const int ty = blockIdx.x;           // 0..HH/RROWS-1
    const int c = blockIdx.y;
    const int b = blockIdx.z;
    const int y0 = ty * RROWS;

    const float* src = (srcSel == 0) ? g_lat : (srcSel == 1 ? g_dA : g_dB);
    float* dst = (dstSel == 1) ? g_dA : g_dB;

    const float* sp = src + (size_t)(b * CC + c) * PLANE;
    for (int r = 0; r < RROWS + 6; r++) {
        const int yy = y0 + r - 3;
        for (int xx = tid; xx < WW + 6; xx += blockDim.x) {
            const int gx = xx - 3;
            sIn[r][xx] = (yy >= 0 && yy < HH && gx >= 0 && gx < WW) ? sp[yy * WW + gx] : 0.f;
        }
    }
    __syncthreads();

    const float* Ebase = g_E + (size_t)(c * KK) * NPIX + (size_t)b * PLANE + (size_t)y0 * WW + tid;
    const float* Sp = g_Sinv + (size_t)b * PLANE + (size_t)y0 * WW + tid;
    float* dp = dst + ((size_t)(b * CC + c) * HH + y0) * WW + tid;

    for (int ry = 0; ry < RROWS; ry++) {
        const float* Ep = Ebase + (size_t)ry * WW;
        float acc0 = 0.f, acc1 = 0.f;
#pragma unroll
        for (int t = 0; t < KK; t++) {
            const float ev = Ep[(size_t)t * NPIX];
            const float dv = sIn[ry + t / KQ][tid + t % KQ];
            if (t & 1) acc1 = fmaf(ev, dv, acc1);
            else       acc0 = fmaf(ev, dv, acc0);
        }
        dp[(size_t)ry * WW] = (acc0 + acc1) * Sp[(size_t)ry * WW];
    }
}

// ================= K7: 1x1 conv (24 -> 1) =================
__global__ void k_out(const float* __restrict__ w_td,
                      const float* __restrict__ b_td,
                      float* __restrict__ out) {
    const int bid = blockIdx.x;          // b*HH + y
    const int b = bid >> 8, y = bid & 255;
    const int tid = threadIdx.x;
    const float* sp = g_dB + (size_t)b * CC * PLANE + (size_t)y * WW + tid;
    float acc = b_td[0];
#pragma unroll
    for (int c = 0; c < CC; c++) acc = fmaf(w_td[c], sp[(size_t)c * PLANE], acc);
    out[(size_t)b * PLANE + (size_t)y * WW + tid] = acc;
}

// ================= host launcher =================
extern "C" void kernel_launch(void* const* d_in, const int* in_sizes, int n_in,
                              void* d_out, int out_size) {
    const float* depth   = (const float*)d_in[0];
    const float* texture = (const float*)d_in[1];
    const float* w_dp    = (const float*)d_in[2];
    const float* b_dp    = (const float*)d_in[3];
    const float* w_kp    = (const float*)d_in[4];
    const float* b_kp    = (const float*)d_in[5];
    const float* w_td    = (const float*)d_in[6];
    const float* b_td    = (const float*)d_in[7];
    float* out = (float*)d_out;

    k_lat<<<BB * HH, 256>>>(depth, w_dp, b_dp);
    k_softmax<<<BB * HH, 256>>>(texture, w_kp, b_kp);

    dim3 gd(HH / RROWS, CC, BB);
    k_diff<<<gd, 256>>>(0, 1);   // lat -> dA
    k_diff<<<gd, 256>>>(1, 2);   // dA  -> dB
    k_diff<<<gd, 256>>>(2, 1);   // dB  -> dA
    k_diff<<<gd, 256>>>(1, 2);   // dA  -> dB

    k_out<<<BB * HH, 256>>>(w_td, b_td, out);
}